// round 17
// baseline (speedup 1.0000x reference)
#include <cuda_runtime.h>
#include <math.h>

// Problem constants
#define B_      32
#define T_      1024
#define NBG     64              // B*G paths
#define NSTEPS  1023
#define DT_     (1.0f/1023.0f)
#define SIG4    84              // 4 + 16 + 64   [S1(4); S2(16,i*4+j); S3(64,(i*4+j)*4+k)]
#define CPP     64              // chunks per path
#define CSTEP   16              // steps per chunk

// Scratch (static device arrays — no allocation)
__device__ __align__(16) float g_lw4[32 * 2 * SIG4];   // transformed weights
__device__ __align__(16) float g_sig4[NBG * SIG4];     // final 4-dim sigs

// ---------------------------------------------------------------------------
// Kernel A: transform lin_w into 4-dim basis.
// lw4[o][g] = lin_w[o, g-block] contracted with M_g^{(x)k}, k=1..3.
// M_g (12x4): row0 = e0 (time); rows1-3 = I3; rows 4+e = [0, W_g[e][0..2]].
// One block per (o,g): 64 blocks x 128 threads.
// ---------------------------------------------------------------------------
__global__ __launch_bounds__(128) void wtrans_kernel(
    const float* __restrict__ lin_w, const float* __restrict__ aug_w)
{
    __shared__ float Msm[12][4];
    __shared__ float T1[576];    // [a][b][k4] = sum_k w3[a,b,k] M[k,k4]
    __shared__ float T2[192];    // [a][j4][k4] = sum_b T1[a,b,k4] M[b,j4]
    __shared__ float U[48];      // [a][j4] = sum_b w2[a,b] M[b,j4]

    int tid = threadIdx.x;
    int o = blockIdx.x >> 1;
    int g = blockIdx.x & 1;
    const float* w = lin_w + (size_t)o * (2 * 1884) + g * 1884;   // [w1(12); w2(144); w3(1728)]

    if (tid < 48) {
        int a = tid / 4, c4 = tid % 4;
        float v;
        if (a == 0)      v = (c4 == 0) ? 1.f : 0.f;
        else if (a < 4)  v = (c4 == a) ? 1.f : 0.f;
        else             v = (c4 > 0) ? aug_w[g * 24 + (a - 4) * 3 + (c4 - 1)] : 0.f;
        Msm[a][c4] = v;
    }
    __syncthreads();

    // T1 and U
    for (int e = tid; e < 576; e += 128) {
        int a = e / 48, b = (e % 48) / 4, k4 = e % 4;
        const float* wr = w + 156 + (a * 12 + b) * 12;
        float s = 0.f;
#pragma unroll
        for (int k = 0; k < 12; k++) s = fmaf(wr[k], Msm[k][k4], s);
        T1[e] = s;
    }
    for (int e = tid; e < 48; e += 128) {
        int a = e / 4, j4 = e % 4;
        const float* wr = w + 12 + a * 12;
        float s = 0.f;
#pragma unroll
        for (int b = 0; b < 12; b++) s = fmaf(wr[b], Msm[b][j4], s);
        U[e] = s;
    }
    __syncthreads();

    // T2
    for (int e = tid; e < 192; e += 128) {
        int a = e / 16, j4 = (e % 16) / 4, k4 = e % 4;
        float s = 0.f;
#pragma unroll
        for (int b = 0; b < 12; b++) s = fmaf(T1[a * 48 + b * 4 + k4], Msm[b][j4], s);
        T2[e] = s;
    }
    __syncthreads();

    // outputs: lw1(4) | lw2(16) | lw3(64)
    float* outp = g_lw4 + (size_t)(o * 2 + g) * SIG4;
    for (int e = tid; e < SIG4; e += 128) {
        float s = 0.f;
        if (e < 4) {
#pragma unroll
            for (int a = 0; a < 12; a++) s = fmaf(w[a], Msm[a][e], s);
        } else if (e < 20) {
            int ij = e - 4, i4 = ij / 4, j4 = ij % 4;
#pragma unroll
            for (int a = 0; a < 12; a++) s = fmaf(U[a * 4 + j4], Msm[a][i4], s);
        } else {
            int ijk = e - 20, i4 = ijk / 16, j4 = (ijk / 4) % 4, k4 = ijk % 4;
#pragma unroll
            for (int a = 0; a < 12; a++) s = fmaf(T2[a * 16 + j4 * 4 + k4], Msm[a][i4], s);
        }
        outp[e] = s;
    }
}

// ---------------------------------------------------------------------------
// Kernel B: 4-dim depth-3 chunk signatures + in-block Chen tree combine.
// Thread = one 16-step chunk (84 register accumulators, no smem in mainloop).
// Block = 128 threads = 2 paths x 64 chunks. Tree combine 64->1 per path.
// Per-step (104 FMA):
//   u_i = de_i/6 + s1_i/2 ; c3_ij = u_i*de_j + s2_ij
//   s3_ijk += c3_ij*de_k ; v_i = de_i/2 + s1_i ; s2_ij += v_i*de_j ; s1_i += de_i
// ---------------------------------------------------------------------------
__global__ __launch_bounds__(128) void sig4_kernel(const float* __restrict__ x)
{
    __shared__ float sh[2][CPP][SIG4];     // 43008 B
    __shared__ float scr[2][32][20];       // 5120 B  (A-side S1,S2 staging)

    int tid = threadIdx.x;
    int lp  = tid >> 6;          // local path 0/1
    int cc  = tid & 63;          // chunk within path
    int bg  = blockIdx.x * 2 + lp;
    int b   = bg >> 1;           // batch index (g only affects weights, not path4)

    // ---- chunk signature in registers ----
    float s1[4], s2[16], s3[64];
#pragma unroll
    for (int q = 0; q < 4; q++)  s1[q] = 0.f;
#pragma unroll
    for (int q = 0; q < 16; q++) s2[q] = 0.f;
#pragma unroll
    for (int q = 0; q < 64; q++) s3[q] = 0.f;

    const float* xb = x + (size_t)b * T_ * 3;
    int t0 = cc * CSTEP;
    float p0 = xb[t0 * 3], p1 = xb[t0 * 3 + 1], p2 = xb[t0 * 3 + 2];

#pragma unroll 1
    for (int t = 0; t < CSTEP; t++) {
        int tt = t0 + t;
        int nidx = (tt < NSTEPS) ? (tt + 1) : NSTEPS;   // clamp: in-bounds load
        float n0 = xb[nidx * 3], n1 = xb[nidx * 3 + 1], n2 = xb[nidx * 3 + 2];
        float de[4];
        de[0] = (tt < NSTEPS) ? DT_ : 0.f;   // dx's auto-zero when clamped
        de[1] = n0 - p0; de[2] = n1 - p1; de[3] = n2 - p2;

#pragma unroll
        for (int i = 0; i < 4; i++) {
            float u = fmaf(de[i], (1.f/6.f), 0.5f * s1[i]);
            float v = fmaf(de[i], 0.5f, s1[i]);
#pragma unroll
            for (int j = 0; j < 4; j++) {
                float c3 = fmaf(u, de[j], s2[i * 4 + j]);
#pragma unroll
                for (int k = 0; k < 4; k++)
                    s3[(i * 4 + j) * 4 + k] = fmaf(c3, de[k], s3[(i * 4 + j) * 4 + k]);
                s2[i * 4 + j] = fmaf(v, de[j], s2[i * 4 + j]);
            }
            s1[i] += de[i];
        }
        p0 = n0; p1 = n1; p2 = n2;
    }

    // stage to smem: [S1; S2; S3]
    {
        float* dst = sh[lp][cc];
#pragma unroll
        for (int q = 0; q < 4; q++)  dst[q] = s1[q];
#pragma unroll
        for (int q = 0; q < 16; q++) dst[4 + q] = s2[q];
#pragma unroll
        for (int q = 0; q < 64; q++) dst[20 + q] = s3[q];
    }
    __syncthreads();

    // ---- tree combine: 6 levels, ordered pairs (Chen) ----
    for (int L = 0; L < 6; L++) {
        int nm  = 32 >> L;           // merges per path
        int tpm = 2 << L;            // threads per merge
        // stage A-side S1,S2 (gets overwritten while still needed)
        for (int idx = cc; idx < nm * 20; idx += 64) {
            int mm = idx / 20, f = idx % 20;
            scr[lp][mm][f] = sh[lp][mm * (2 << L)][f];
        }
        __syncthreads();

        int m  = cc / tpm;
        int el = cc % tpm;
        float* A = sh[lp][m * (2 << L)];
        const float* Bs = sh[lp][m * (2 << L) + (1 << L)];
        const float* As = scr[lp][m];
        for (int e = el; e < SIG4; e += tpm) {
            if (e < 4) {
                A[e] = As[e] + Bs[e];
            } else if (e < 20) {
                int ij = e - 4, i = ij / 4, j = ij % 4;
                A[e] = As[e] + Bs[e] + As[i] * Bs[j];
            } else {
                int ijk = e - 20, i = ijk / 16, j = (ijk / 4) % 4, k = ijk % 4;
                A[e] = A[e] + Bs[e] + As[i] * Bs[4 + j * 4 + k]
                     + As[4 + i * 4 + j] * Bs[k];
            }
        }
        __syncthreads();
    }

    // write final sig4 for this path
    for (int e = cc; e < SIG4; e += 64)
        g_sig4[(size_t)bg * SIG4 + e] = sh[lp][0][e];
}

// ---------------------------------------------------------------------------
// Kernel C: out[b][o] = sigmoid( sum_g lw4[o][g] . sig4[b*2+g] + lin_b[o] )
// 32 blocks (b) x 32 threads (o).
// ---------------------------------------------------------------------------
__global__ __launch_bounds__(32) void out4_kernel(
    const float* __restrict__ lin_b, float* __restrict__ out)
{
    __shared__ float ss[2 * SIG4];
    int b = blockIdx.x;
    int tid = threadIdx.x;
    for (int e = tid; e < 2 * SIG4; e += 32)
        ss[e] = g_sig4[(size_t)b * 2 * SIG4 + e];
    __syncthreads();

    int o = tid;
    float acc = lin_b[o];
#pragma unroll
    for (int g = 0; g < 2; g++) {
        const float* lw = g_lw4 + (size_t)(o * 2 + g) * SIG4;
        const float* sg = ss + g * SIG4;
#pragma unroll 4
        for (int e = 0; e < SIG4; e++)
            acc = fmaf(lw[e], sg[e], acc);
    }
    out[b * 32 + o] = 1.0f / (1.0f + expf(-acc));
}

// ---------------------------------------------------------------------------
extern "C" void kernel_launch(void* const* d_in, const int* in_sizes, int n_in,
                              void* d_out, int out_size)
{
    const float* x     = (const float*)d_in[0];  // (32,1024,3)
    const float* aug_w = (const float*)d_in[1];  // (2,8,3)
    // d_in[2] = aug_b — unused (bias cancels in path increments)
    const float* lin_w = (const float*)d_in[3];  // (32, 3768)
    const float* lin_b = (const float*)d_in[4];  // (32,)
    float* out = (float*)d_out;                  // (32,32)

    wtrans_kernel<<<64, 128>>>(lin_w, aug_w);
    sig4_kernel<<<NBG / 2, 128>>>(x);
    out4_kernel<<<B_, 32>>>(lin_b, out);
}